// round 7
// baseline (speedup 1.0000x reference)
#include <cuda_runtime.h>

// SpatialWeightsEsDot on GB300.
//   phi = w_phi @ u (1x1 conv), layout [b][c][y][x]
//   M_{dy,dx}[b][y][x] = sum_c phi[b,c,y,x]*phi[b,c,y+dy,x+dx]  (zero outside image)
//   score[p,d] = 1[p+d in image] * sum_{e in 3x3} M_d[p+e]
//   out = softmax over the 49 offsets -> [2,128,128,1,49]

#define HH 128
#define WW 128
#define CC 64

__device__ float g_phi[2 * CC * HH * WW];     // [b][c][y][x]
__device__ float g_M[49 * 2 * HH * WW];       // [off][b][y][x], off=(dy+3)*7+(dx+3)

typedef unsigned long long u64;

__device__ __forceinline__ void ffma2(u64& d, u64 a, u64 b) {
    asm("fma.rn.f32x2 %0, %1, %2, %3;" : "=l"(d) : "l"(a), "l"(b), "l"(d));
}

// ---------------------------------------------------------------------------
// K1: phi. 512 blocks x 256 thr. Warp = og (8 output channels), lane = 2 px.
// w held in smem as duplicated f32x2 pairs {w,w}; u loaded once per block-32px
// per channel (8 og warps share via L1). Inner k-step: 1 LDG.64 + 4 LDS.128
// (broadcast) + 8 FFMA2.
// ---------------------------------------------------------------------------
__global__ void __launch_bounds__(256)
phi_kernel(const float* __restrict__ u, const float* __restrict__ w) {
    __shared__ float2 s_w2[CC * CC];           // [k][o] duplicated pairs, 32KB
    int tid = threadIdx.x;
    for (int i = tid; i < CC * CC; i += 256) {
        int k = i >> 6, o = i & 63;
        float v = w[o * CC + k];
        s_w2[i] = make_float2(v, v);
    }
    __syncthreads();

    int lane = tid & 31;
    int og   = tid >> 5;                       // 0..7 -> outputs og*8..og*8+7
    int pg   = blockIdx.x * 32 + lane;         // pixel-pair index, 0..16383
    int b    = pg >> 13;
    int p    = (pg & 8191) << 1;               // pixel offset within image

    const u64* ub = (const u64*)(u + (size_t)b * CC * 16384 + p);  // +k*8192 (in u64)

    u64 acc[8];
#pragma unroll
    for (int j = 0; j < 8; j++) acc[j] = 0ull;

#pragma unroll 8
    for (int k = 0; k < CC; k++) {
        u64 u2 = ub[(size_t)k * 8192];
        const ulonglong2* wp = (const ulonglong2*)&s_w2[k * CC + og * 8];
        ulonglong2 w01 = wp[0];
        ulonglong2 w23 = wp[1];
        ulonglong2 w45 = wp[2];
        ulonglong2 w67 = wp[3];
        ffma2(acc[0], u2, w01.x); ffma2(acc[1], u2, w01.y);
        ffma2(acc[2], u2, w23.x); ffma2(acc[3], u2, w23.y);
        ffma2(acc[4], u2, w45.x); ffma2(acc[5], u2, w45.y);
        ffma2(acc[6], u2, w67.x); ffma2(acc[7], u2, w67.y);
    }

    float* op = g_phi + ((size_t)b * CC + og * 8) * 16384 + p;
#pragma unroll
    for (int j = 0; j < 8; j++)
        *(u64*)(op + (size_t)j * 16384) = acc[j];
}

// ---------------------------------------------------------------------------
// K2: M maps. grid (256 rows, 2 dy-halves), block 128 = 4 warps (dy groups).
// Lane = 4 consecutive pixels. Per channel: 1 center LDG.128 + 3 shifted
// LDG.128 -> 12-float register window serves all 7 dx via shifted FMAs.
// ---------------------------------------------------------------------------
__global__ void __launch_bounds__(128)
m_kernel() {
    int lane = threadIdx.x & 31;
    int grp  = (threadIdx.x >> 5) + blockIdx.y * 4;  // 0..6 -> dy = grp-3
    if (grp >= 7) return;                            // idle 4th warp of half 1
    int row  = blockIdx.x;                           // 0..255
    int b = row >> 7, y = row & 127;
    int dy = grp - 3;
    int x  = lane << 2;
    int ys = y + dy;
    bool rowok = (unsigned)ys < (unsigned)HH;
    bool lok = (x > 0);
    bool rok = (x < WW - 4);

    const float* pcb = g_phi + b * CC * 16384 + y  * WW + x;   // +c*16384
    const float* psb = g_phi + b * CC * 16384 + ys * WW + x;

    float acc[28];
#pragma unroll
    for (int i = 0; i < 28; i++) acc[i] = 0.f;

#pragma unroll 4
    for (int c = 0; c < CC; c++) {
        const float* pc_ = pcb + c * 16384;
        const float* ps_ = psb + c * 16384;
        float4 ctr = *(const float4*)pc_;
        float4 w0 = make_float4(0.f, 0.f, 0.f, 0.f);
        float4 w1 = w0, w2 = w0;
        if (rowok) {
            w1 = *(const float4*)ps_;
            if (lok) w0 = *(const float4*)(ps_ - 4);
            if (rok) w2 = *(const float4*)(ps_ + 4);
        }
        float win[12] = {w0.x, w0.y, w0.z, w0.w,
                         w1.x, w1.y, w1.z, w1.w,
                         w2.x, w2.y, w2.z, w2.w};
        float ct[4] = {ctr.x, ctr.y, ctr.z, ctr.w};
#pragma unroll
        for (int d = 0; d < 7; d++)            // dx = d-3
#pragma unroll
            for (int j = 0; j < 4; j++)
                acc[d * 4 + j] += ct[j] * win[1 + d + j];   // phi_s[x+j+(d-3)]
    }

    float* mb = g_M + b * 16384 + y * WW + x;
#pragma unroll
    for (int d = 0; d < 7; d++)
        *(float4*)(mb + (size_t)(grp * 7 + d) * 32768) =
            make_float4(acc[d * 4], acc[d * 4 + 1], acc[d * 4 + 2], acc[d * 4 + 3]);
}

// ---------------------------------------------------------------------------
// K3: boxsum + mask + softmax. grid (2 xb, 128 y, 2 b), block 512.
// Thread (px 0..63, dyg 0..7; dyg==7 idle in compute). Lanes = consecutive x
// -> coalesced M reads. Cross-dy softmax via tiny smem reduction (pitch 9).
// ---------------------------------------------------------------------------
__global__ void __launch_bounds__(512)
attn_kernel(float* __restrict__ out) {
    __shared__ float s_red[64 * 9];
    int t   = threadIdx.x;
    int px  = t & 63;
    int dyg = t >> 6;                          // 0..7
    int b = blockIdx.z, y = blockIdx.y, x = blockIdx.x * 64 + px;

    float sc[7];
    float lmax = -1e30f;
    if (dyg < 7) {
        int dy = dyg - 3;
#pragma unroll
        for (int d3 = 0; d3 < 7; d3++) {
            int dx = d3 - 3;
            float s = 0.f;
            const float* mb = g_M + (size_t)(dyg * 7 + d3) * 32768 + b * 16384;
#pragma unroll
            for (int ey = -1; ey <= 1; ey++) {
                int yy = y + ey;
                if ((unsigned)yy < (unsigned)HH) {
#pragma unroll
                    for (int ex = -1; ex <= 1; ex++) {
                        int xx = x + ex;
                        if ((unsigned)xx < (unsigned)WW) s += mb[yy * WW + xx];
                    }
                }
            }
            bool valid = ((unsigned)(y + dy) < (unsigned)HH) &&
                         ((unsigned)(x + dx) < (unsigned)WW);
            sc[d3] = valid ? s : 0.f;
            lmax = fmaxf(lmax, sc[d3]);
        }
    }
    s_red[px * 9 + dyg] = lmax;                // dyg==7 writes -1e30 (ignored)
    __syncthreads();

    float gmax = s_red[px * 9 + 0];
#pragma unroll
    for (int j = 1; j < 7; j++) gmax = fmaxf(gmax, s_red[px * 9 + j]);

    float e[7];
    float lsum = 0.f;
    if (dyg < 7) {
#pragma unroll
        for (int d3 = 0; d3 < 7; d3++) { e[d3] = __expf(sc[d3] - gmax); lsum += e[d3]; }
    }
    __syncthreads();                           // protect s_red before overwrite
    s_red[px * 9 + dyg] = lsum;                // dyg==7 writes 0 (lsum init, not read)
    __syncthreads();

    float gsum = 0.f;
#pragma unroll
    for (int j = 0; j < 7; j++) gsum += s_red[px * 9 + j];

    if (dyg < 7) {
        float inv = 1.0f / gsum;
        float* op = out + (size_t)(b * 16384 + y * WW + x) * 49 + dyg * 7;
#pragma unroll
        for (int d3 = 0; d3 < 7; d3++) op[d3] = e[d3] * inv;
    }
}

extern "C" void kernel_launch(void* const* d_in, const int* in_sizes, int n_in,
                              void* d_out, int out_size) {
    const float* u = (const float*)d_in[0];    // [2,64,128,128]
    const float* w = (const float*)d_in[1];    // [64,64]
    float* out = (float*)d_out;                // [2,128,128,1,49]

    phi_kernel<<<512, 256>>>(u, w);
    m_kernel<<<dim3(256, 2), 128>>>();
    attn_kernel<<<dim3(2, 128, 2), 512>>>(out);
}

// round 9
// speedup vs baseline: 1.0712x; 1.0712x over previous
#include <cuda_runtime.h>

// SpatialWeightsEsDot on GB300.
//   phi = w_phi @ u (1x1 conv), layout [b][c][y][x]
//   M_{dy,dx}[b][y][x] = sum_c phi[b,c,y,x]*phi[b,c,y+dy,x+dx]  (zero outside image)
//   score[p,d] = 1[p+d in image] * sum_{e in 3x3} M_d[p+e]
//   out = softmax over the 49 offsets -> [2,128,128,1,49]

#define HH 128
#define WW 128
#define CC 64

__device__ float g_phi[2 * CC * HH * WW];     // [b][c][y][x]
__device__ float g_M[49 * 2 * HH * WW];       // [off][b][y][x], off=(dy+3)*7+(dx+3)

typedef unsigned long long u64;

__device__ __forceinline__ void ffma2(u64& d, u64 a, u64 b) {
    asm("fma.rn.f32x2 %0, %1, %2, %3;" : "=l"(d) : "l"(a), "l"(b), "l"(d));
}
__device__ __forceinline__ u64 dup2(float v) {
    u64 d; asm("mov.b64 %0, {%1, %1};" : "=l"(d) : "f"(v)); return d;
}

// ---------------------------------------------------------------------------
// K1: phi, register-tiled. Thread tile = 8 outputs x 4 pixels.
// Per k-step: 1 LDG.128 (u, coalesced) + 2 LDS.128 (w, broadcast) + 8 dup-MOV
// + 16 FFMA2 -> 32 lane-FMAs per 3 memory ops (L1-wavefront pressure ~6x lower
// than previous design). grid (256 px-blocks, 2 out-halves) x 128 thr.
// ---------------------------------------------------------------------------
__global__ void __launch_bounds__(128)
phi_kernel(const float* __restrict__ u, const float* __restrict__ w) {
    __shared__ float s_wT[CC * CC];            // [k][o] transposed
    int tid = threadIdx.x;
    for (int i = tid; i < CC * CC; i += 128) {
        int k = i >> 6, o = i & 63;
        s_wT[i] = w[o * CC + k];
    }
    __syncthreads();

    int og    = tid >> 5;                      // 0..3
    int pxq   = tid & 31;                      // 0..31 (32 px-quads / block)
    int obase = blockIdx.y * 32 + og * 8;      // 8 outputs per thread
    int pix   = blockIdx.x * 128 + pxq * 4;    // 4 consecutive pixels
    int b     = pix >> 14;
    int p     = pix & 16383;

    const float4* ub = (const float4*)(u + (size_t)b * CC * 16384 + p); // +k*4096
    const float4* w4 = (const float4*)s_wT;    // [k][o/4]
    int wbase = obase >> 2;

    u64 acc[8][2];
#pragma unroll
    for (int j = 0; j < 8; j++) { acc[j][0] = 0ull; acc[j][1] = 0ull; }

#pragma unroll 4
    for (int k = 0; k < CC; k++) {
        longlong2 uv = *(const longlong2*)&ub[(size_t)k * 4096];
        u64 u01 = (u64)uv.x;                   // pixels p, p+1
        u64 u23 = (u64)uv.y;                   // pixels p+2, p+3
        float4 wa = w4[k * 16 + wbase];
        float4 wb = w4[k * 16 + wbase + 1];
        u64 wd0 = dup2(wa.x), wd1 = dup2(wa.y), wd2 = dup2(wa.z), wd3 = dup2(wa.w);
        u64 wd4 = dup2(wb.x), wd5 = dup2(wb.y), wd6 = dup2(wb.z), wd7 = dup2(wb.w);
        ffma2(acc[0][0], u01, wd0); ffma2(acc[0][1], u23, wd0);
        ffma2(acc[1][0], u01, wd1); ffma2(acc[1][1], u23, wd1);
        ffma2(acc[2][0], u01, wd2); ffma2(acc[2][1], u23, wd2);
        ffma2(acc[3][0], u01, wd3); ffma2(acc[3][1], u23, wd3);
        ffma2(acc[4][0], u01, wd4); ffma2(acc[4][1], u23, wd4);
        ffma2(acc[5][0], u01, wd5); ffma2(acc[5][1], u23, wd5);
        ffma2(acc[6][0], u01, wd6); ffma2(acc[6][1], u23, wd6);
        ffma2(acc[7][0], u01, wd7); ffma2(acc[7][1], u23, wd7);
    }

    float* op = g_phi + ((size_t)b * CC + obase) * 16384 + p;
#pragma unroll
    for (int j = 0; j < 8; j++) {
        *(u64*)(op + (size_t)j * 16384)     = acc[j][0];
        *(u64*)(op + (size_t)j * 16384 + 2) = acc[j][1];
    }
}

// ---------------------------------------------------------------------------
// K2: M maps. grid (256 rows, 2 dy-halves), block 128 = 4 warps (dy groups).
// Lane = 4 consecutive pixels. Per channel: 1 center LDG.128 + 3 shifted
// LDG.128 -> 12-float register window serves all 7 dx via shifted FMAs.
// ---------------------------------------------------------------------------
__global__ void __launch_bounds__(128)
m_kernel() {
    int lane = threadIdx.x & 31;
    int grp  = (threadIdx.x >> 5) + blockIdx.y * 4;  // 0..6 -> dy = grp-3
    if (grp >= 7) return;                            // idle 4th warp of half 1
    int row  = blockIdx.x;                           // 0..255
    int b = row >> 7, y = row & 127;
    int dy = grp - 3;
    int x  = lane << 2;
    int ys = y + dy;
    bool rowok = (unsigned)ys < (unsigned)HH;
    bool lok = (x > 0);
    bool rok = (x < WW - 4);

    const float* pcb = g_phi + b * CC * 16384 + y  * WW + x;   // +c*16384
    const float* psb = g_phi + b * CC * 16384 + ys * WW + x;

    float acc[28];
#pragma unroll
    for (int i = 0; i < 28; i++) acc[i] = 0.f;

#pragma unroll 4
    for (int c = 0; c < CC; c++) {
        const float* pc_ = pcb + c * 16384;
        const float* ps_ = psb + c * 16384;
        float4 ctr = *(const float4*)pc_;
        float4 w0 = make_float4(0.f, 0.f, 0.f, 0.f);
        float4 w1 = w0, w2 = w0;
        if (rowok) {
            w1 = *(const float4*)ps_;
            if (lok) w0 = *(const float4*)(ps_ - 4);
            if (rok) w2 = *(const float4*)(ps_ + 4);
        }
        float win[12] = {w0.x, w0.y, w0.z, w0.w,
                         w1.x, w1.y, w1.z, w1.w,
                         w2.x, w2.y, w2.z, w2.w};
        float ct[4] = {ctr.x, ctr.y, ctr.z, ctr.w};
#pragma unroll
        for (int d = 0; d < 7; d++)            // dx = d-3
#pragma unroll
            for (int j = 0; j < 4; j++)
                acc[d * 4 + j] += ct[j] * win[1 + d + j];   // phi_s[x+j+(d-3)]
    }

    float* mb = g_M + b * 16384 + y * WW + x;
#pragma unroll
    for (int d = 0; d < 7; d++)
        *(float4*)(mb + (size_t)(grp * 7 + d) * 32768) =
            make_float4(acc[d * 4], acc[d * 4 + 1], acc[d * 4 + 2], acc[d * 4 + 3]);
}

// ---------------------------------------------------------------------------
// K3: boxsum + mask + softmax. grid (2 xb, 128 y, 2 b), block 512.
// Thread (px 0..63, dyg 0..7; dyg==7 idle in compute). Lanes = consecutive x
// -> coalesced M reads. Cross-dy softmax via tiny smem reduction (pitch 9).
// ---------------------------------------------------------------------------
__global__ void __launch_bounds__(512)
attn_kernel(float* __restrict__ out) {
    __shared__ float s_red[64 * 9];
    int t   = threadIdx.x;
    int px  = t & 63;
    int dyg = t >> 6;                          // 0..7
    int b = blockIdx.z, y = blockIdx.y, x = blockIdx.x * 64 + px;

    float sc[7];
    float lmax = -1e30f;
    if (dyg < 7) {
        int dy = dyg - 3;
#pragma unroll
        for (int d3 = 0; d3 < 7; d3++) {
            int dx = d3 - 3;
            float s = 0.f;
            const float* mb = g_M + (size_t)(dyg * 7 + d3) * 32768 + b * 16384;
#pragma unroll
            for (int ey = -1; ey <= 1; ey++) {
                int yy = y + ey;
                if ((unsigned)yy < (unsigned)HH) {
#pragma unroll
                    for (int ex = -1; ex <= 1; ex++) {
                        int xx = x + ex;
                        if ((unsigned)xx < (unsigned)WW) s += mb[yy * WW + xx];
                    }
                }
            }
            bool valid = ((unsigned)(y + dy) < (unsigned)HH) &&
                         ((unsigned)(x + dx) < (unsigned)WW);
            sc[d3] = valid ? s : 0.f;
            lmax = fmaxf(lmax, sc[d3]);
        }
    }
    s_red[px * 9 + dyg] = lmax;                // dyg==7 writes -1e30 (ignored)
    __syncthreads();

    float gmax = s_red[px * 9 + 0];
#pragma unroll
    for (int j = 1; j < 7; j++) gmax = fmaxf(gmax, s_red[px * 9 + j]);

    float e[7];
    float lsum = 0.f;
    if (dyg < 7) {
#pragma unroll
        for (int d3 = 0; d3 < 7; d3++) { e[d3] = __expf(sc[d3] - gmax); lsum += e[d3]; }
    }
    __syncthreads();                           // protect s_red before overwrite
    s_red[px * 9 + dyg] = lsum;                // dyg==7 writes 0 (lsum init, not read)
    __syncthreads();

    float gsum = 0.f;
#pragma unroll
    for (int j = 0; j < 7; j++) gsum += s_red[px * 9 + j];

    if (dyg < 7) {
        float inv = 1.0f / gsum;
        float* op = out + (size_t)(b * 16384 + y * WW + x) * 49 + dyg * 7;
#pragma unroll
        for (int d3 = 0; d3 < 7; d3++) op[d3] = e[d3] * inv;
    }
}

extern "C" void kernel_launch(void* const* d_in, const int* in_sizes, int n_in,
                              void* d_out, int out_size) {
    const float* u = (const float*)d_in[0];    // [2,64,128,128]
    const float* w = (const float*)d_in[1];    // [64,64]
    float* out = (float*)d_out;                // [2,128,128,1,49]

    phi_kernel<<<dim3(256, 2), 128>>>(u, w);
    m_kernel<<<dim3(256, 2), 128>>>();
    attn_kernel<<<dim3(2, 128, 2), 512>>>(out);
}